// round 9
// baseline (speedup 1.0000x reference)
#include <cuda_runtime.h>
#include <cuda_fp16.h>
#include <cuda_bf16.h>
#include <stdint.h>

// Problem constants (fixed by the dataset).
#define N_NODES 65536
#define N_EDGES 1048576
#define D 64

#define GEMM_BLOCKS (N_NODES / 128)            // 512
#define DEG_BLOCKS  (N_EDGES / 4 / 256)        // 1024

// Scratch: __device__ globals (no allocation allowed in kernel_launch).
__device__ __align__(16) float  g_h[N_NODES * D];    // h = x @ W, fp32 (16 MB)
__device__ __align__(16) __half g_h16[N_NODES * D];  // h in fp16 (8 MB) for gather
__device__ float g_dinv[N_NODES];                    // deg^{-1/2} (incl. self-loop)
__device__ int   g_deg[N_NODES];                     // in-degree WITHOUT self-loop

// ---------------------------------------------------------------------------
// Fused kernel: blocks [0,512) run the GEMM mainloop (h = x @ W -> g_h/g_h16);
// blocks [512,1536) run the degree count (hidden under the GEMM).
__global__ __launch_bounds__(256) void k_fused(const float* __restrict__ x,
                                               const float* __restrict__ W,
                                               const int* __restrict__ ei) {
    __shared__ __align__(16) float xs[64 * 128];  // transposed: xs[k*128 + row]
    __shared__ __align__(16) float ws[64 * 64];   // row-major: ws[k*64 + j]

    const int tid = threadIdx.x;

    if (blockIdx.x >= GEMM_BLOCKS) {
        // ---- degree-count phase: 4 edges per thread via int4 ----
        int t = (blockIdx.x - GEMM_BLOCKS) * 256 + tid;
        int4 d = ((const int4*)(ei + N_EDGES))[t];
        atomicAdd(&g_deg[d.x], 1);
        atomicAdd(&g_deg[d.y], 1);
        atomicAdd(&g_deg[d.z], 1);
        atomicAdd(&g_deg[d.w], 1);
        return;
    }

    // ---- GEMM phase: 128-row tile, 8x4 micro-tile per thread ----
    const int rowBase = blockIdx.x * 128;

    {
        const float4* Wv = (const float4*)W;
        float4* wsv = (float4*)ws;
        #pragma unroll
        for (int q = 0; q < 4; q++) wsv[tid + q * 256] = Wv[tid + q * 256];
    }
    {
        int row = tid & 127;
        int kq  = tid >> 7;  // 0..1
        const float4* xrow = (const float4*)&x[(size_t)(rowBase + row) * D];
        #pragma unroll
        for (int q = 0; q < 8; q++) {
            int k0 = kq * 32 + q * 4;
            float4 v = xrow[k0 >> 2];
            xs[(k0 + 0) * 128 + row] = v.x;
            xs[(k0 + 1) * 128 + row] = v.y;
            xs[(k0 + 2) * 128 + row] = v.z;
            xs[(k0 + 3) * 128 + row] = v.w;
        }
    }
    __syncthreads();

    const int ty = tid >> 4;   // 0..15 -> rows ty*8 .. ty*8+7
    const int tx = tid & 15;   // 0..15 -> cols tx*4 .. tx*4+3

    float acc[8][4] = {};
    #pragma unroll 8
    for (int k = 0; k < 64; k++) {
        float4 a0 = *(const float4*)&xs[k * 128 + ty * 8];
        float4 a1 = *(const float4*)&xs[k * 128 + ty * 8 + 4];
        float4 w4 = *(const float4*)&ws[k * 64 + tx * 4];
        float av[8] = {a0.x, a0.y, a0.z, a0.w, a1.x, a1.y, a1.z, a1.w};
        #pragma unroll
        for (int i = 0; i < 8; i++) {
            acc[i][0] += av[i] * w4.x;
            acc[i][1] += av[i] * w4.y;
            acc[i][2] += av[i] * w4.z;
            acc[i][3] += av[i] * w4.w;
        }
    }

    #pragma unroll
    for (int i = 0; i < 8; i++) {
        int r = rowBase + ty * 8 + i;
        float4 hv = make_float4(acc[i][0], acc[i][1], acc[i][2], acc[i][3]);
        *(float4*)&g_h[(size_t)r * D + tx * 4] = hv;
        // fp16 mirror for the scatter gather (halves gather bytes).
        union { __half2 h2[2]; uint2 u; } pk;
        pk.h2[0] = __floats2half2_rn(hv.x, hv.y);
        pk.h2[1] = __floats2half2_rn(hv.z, hv.w);
        *(uint2*)&g_h16[(size_t)r * D + tx * 4] = pk.u;
    }
}

// ---------------------------------------------------------------------------
// Finish kernel: dinv = rsqrt(deg+1); out = h*dinv^2 + b (self-loop + bias).
// Full fp32 path — unchanged precision for the self-loop term.
__global__ __launch_bounds__(256) void k_finish(const float* __restrict__ b,
                                                float* __restrict__ out) {
    int t = blockIdx.x * blockDim.x + threadIdx.x;
    int node = t >> 4;
    int j4   = (t & 15) * 4;

    float di = rsqrtf((float)(g_deg[node] + 1));
    if ((t & 15) == 0) g_dinv[node] = di;
    float s = di * di;

    float4 hv = *(const float4*)&g_h[(size_t)node * D + j4];
    float4 bv = *(const float4*)&b[j4];
    *(float4*)&out[(size_t)node * D + j4] =
        make_float4(hv.x * s + bv.x, hv.y * s + bv.y,
                    hv.z * s + bv.z, hv.w * s + bv.w);
}

// ---------------------------------------------------------------------------
// Edge scatter: 16 lanes per edge; each lane gathers 4 halves (8B, halving
// gather bytes vs fp32), converts to fp32, and issues ONE red.global.add.v4.f32
// (atomic path identical to the proven version).
__global__ __launch_bounds__(256) void k_scatter(const int* __restrict__ ei,
                                                 float* __restrict__ out) {
    long long t = (long long)blockIdx.x * blockDim.x + threadIdx.x;
    int e  = (int)(t >> 4);
    int j4 = ((int)t & 15) * 4;
    if (e >= N_EDGES) return;

    int src = ei[e];
    int dst = ei[N_EDGES + e];
    float norm = g_dinv[src] * g_dinv[dst];

    uint2 raw = *(const uint2*)&g_h16[(size_t)src * D + j4];
    __half2 h01 = *(__half2*)&raw.x;
    __half2 h23 = *(__half2*)&raw.y;
    float2 f01 = __half22float2(h01);
    float2 f23 = __half22float2(h23);
    float4 m = make_float4(f01.x * norm, f01.y * norm,
                           f23.x * norm, f23.y * norm);

    float* p = &out[(size_t)dst * D + j4];
    asm volatile("red.global.add.v4.f32 [%0], {%1, %2, %3, %4};"
                 :: "l"(p), "f"(m.x), "f"(m.y), "f"(m.z), "f"(m.w)
                 : "memory");
}

// ---------------------------------------------------------------------------
extern "C" void kernel_launch(void* const* d_in, const int* in_sizes, int n_in,
                              void* d_out, int out_size) {
    const float* x  = (const float*)d_in[0];
    const int*   ei = (const int*)d_in[1];    // [2, E] int32
    const float* W  = (const float*)d_in[2];
    const float* b  = (const float*)d_in[3];
    float* out = (float*)d_out;

    (void)in_sizes; (void)n_in; (void)out_size;

    void* deg_ptr = nullptr;
    cudaGetSymbolAddress(&deg_ptr, g_deg);
    cudaMemsetAsync(deg_ptr, 0, N_NODES * sizeof(int));

    k_fused<<<GEMM_BLOCKS + DEG_BLOCKS, 256>>>(x, W, ei);
    k_finish<<<(N_NODES * 16) / 256, 256>>>(b, out);

    long long scatter_threads = (long long)N_EDGES * 16;
    k_scatter<<<(unsigned)((scatter_threads + 255) / 256), 256>>>(ei, out);
}